// round 6
// baseline (speedup 1.0000x reference)
#include <cuda_runtime.h>

#define TT 2048
#define NB 512
#define FULLM 0xFFFFFFFFu
typedef unsigned long long ull;

__device__ __forceinline__ float tanhap(float x) {
    float r; asm("tanh.approx.f32 %0, %1;" : "=f"(r) : "f"(x)); return r;
}
__device__ __forceinline__ ull pk(float lo, float hi) {
    ull r; asm("mov.b64 %0, {%1, %2};" : "=l"(r) : "f"(lo), "f"(hi)); return r;
}
__device__ __forceinline__ void upk(ull v, float& lo, float& hi) {
    asm("mov.b64 {%0, %1}, %2;" : "=f"(lo), "=f"(hi) : "l"(v));
}
__device__ __forceinline__ ull fma2(ull a, ull b, ull c) {
    ull d; asm("fma.rn.f32x2 %0, %1, %2, %3;" : "=l"(d) : "l"(a), "l"(b), "l"(c)); return d;
}
__device__ __forceinline__ ull d2l(double d) { return (ull)__double_as_longlong(d); }

__device__ __forceinline__ void cp_async4(void* smem_dst, const void* gmem_src) {
    unsigned saddr = (unsigned)__cvta_generic_to_shared(smem_dst);
    asm volatile("cp.async.ca.shared.global [%0], [%1], 4;\n"
                 :: "r"(saddr), "l"(gmem_src) : "memory");
}
__device__ __forceinline__ void cp_commit() {
    asm volatile("cp.async.commit_group;\n" ::: "memory");
}
__device__ __forceinline__ void cp_wait1() {
    asm volatile("cp.async.wait_group 1;\n" ::: "memory");
}

__global__ void __launch_bounds__(32)
lstm_warpseq4(const float* __restrict__ x,
              const float* __restrict__ W_ih,
              const float* __restrict__ W_hh,
              const float* __restrict__ b_ih,
              const float* __restrict__ b_hh,
              const float* __restrict__ fc_w,
              const float* __restrict__ fc_b,
              float* __restrict__ out)
{
    // 16-deep x ring; rows padded to 16 floats, pads stay zero.
    __shared__ __align__(16) float xring[16][16];

    const int lane = threadIdx.x & 31;
    const int seq  = blockIdx.x;
    const float* xb = x + (size_t)seq * TT * 13;
    float* ob = out + (size_t)seq * TT;

    // Zero the whole ring once (cp.async only ever writes [0..12]).
    #pragma unroll
    for (int i = 0; i < 8; i++)
        reinterpret_cast<float*>(xring)[i * 32 + lane] = 0.0f;

    // Gate assignment: lane L<26: A = gate L (sigmoid: i for L<13, f for L>=13),
    // B = gate 26+L (g=tanh for L<13, o=sigmoid for 13<=L<26).
    // Lane 26: B-dot is the FC head (x-weights 0, h-weights 0.5*fc_w, bias 0.5*fc_b).
    // Sigmoid pre-scale 0.5 folded into weights: act = m*tanh(pre) + a.
    float whA[13], whB[13];           // h-weights kept SCALAR (consumed per-shfl)
    float wiA[13], wiB[13];
    float biasA = 0.0f, biasB = 0.0f;
    {
        const bool g26 = (lane < 26);
        const float sA = 0.5f;
        const float sB = (lane < 13) ? 1.0f : 0.5f;
        const int rA = g26 ? lane : 0;
        const int rB = g26 ? lane + 26 : 0;
        #pragma unroll
        for (int k = 0; k < 13; k++) {
            wiA[k] = g26 ? sA * W_ih[rA * 13 + k] : 0.0f;
            whA[k] = g26 ? sA * W_hh[rA * 13 + k] : 0.0f;
            wiB[k] = g26 ? sB * W_ih[rB * 13 + k] : 0.0f;
            whB[k] = g26 ? sB * W_hh[rB * 13 + k] : 0.0f;
        }
        if (g26) {
            biasA = sA * (b_ih[rA] + b_hh[rA]);
            biasB = sB * (b_ih[rB] + b_hh[rB]);
        }
        if (lane == 26) {
            #pragma unroll
            for (int k = 0; k < 13; k++) { wiB[k] = 0.0f; whB[k] = 0.5f * fc_w[k]; }
            biasB = 0.5f * fc_b[0];
        }
    }

    // Pack x-weights pairwise (7 pairs, last padded with 0).
    ull wxA[7], wxB[7];
    #pragma unroll
    for (int p = 0; p < 6; p++) {
        wxA[p] = pk(wiA[2*p], wiA[2*p+1]);
        wxB[p] = pk(wiB[2*p], wiB[2*p+1]);
    }
    wxA[6] = pk(wiA[12], 0.0f);
    wxB[6] = pk(wiB[12], 0.0f);

    const ull biasPA = pk(biasA, 0.0f);
    const ull biasPB = pk(biasB, 0.0f);
    const ull z64    = pk(0.0f, 0.0f);

    const float mB = (lane < 13) ? 1.0f : 0.5f;
    const float aB = (lane < 13) ? 0.0f : 0.5f;

    float h = 0.0f, c = 0.0f;

    // Prologue: stage rows 0..7 as ONE commit group.
    #pragma unroll
    for (int r = 0; r < 8; r++)
        if (lane < 13) cp_async4(&xring[r][lane], xb + r * 13 + lane);
    cp_commit();

// One LSTM step reading x from compile-time ring SLOT.
#define STEP(SLOT, TTC) do {                                                   \
    const double2* xr = reinterpret_cast<const double2*>(&xring[(SLOT)][0]);   \
    const double2 q0 = xr[0], q1 = xr[1], q2 = xr[2];                          \
    const double  q3 = *reinterpret_cast<const double*>(&xring[(SLOT)][12]);   \
    const ull xp0 = d2l(q0.x), xp1 = d2l(q0.y), xp2 = d2l(q1.x),               \
              xp3 = d2l(q1.y), xp4 = d2l(q2.x), xp5 = d2l(q2.y),               \
              xp6 = d2l(q3);                                                   \
    float hk[13];                                                              \
    _Pragma("unroll")                                                          \
    for (int k = 0; k < 13; k++) hk[k] = __shfl_sync(FULLM, h, k);             \
    /* gate A: packed x-part -> 4 scalar seeds -> scalar h chains */           \
    ull caA = fma2(xp0, wxA[0], biasPA);                                       \
    ull cbA = fma2(xp1, wxA[1], z64);                                          \
    caA = fma2(xp2, wxA[2], caA);                                              \
    cbA = fma2(xp3, wxA[3], cbA);                                              \
    caA = fma2(xp4, wxA[4], caA);                                              \
    cbA = fma2(xp5, wxA[5], cbA);                                              \
    caA = fma2(xp6, wxA[6], caA);                                              \
    float sA0, sA1, sA2, sA3;                                                  \
    upk(caA, sA0, sA1); upk(cbA, sA2, sA3);                                    \
    ull caB = fma2(xp0, wxB[0], biasPB);                                       \
    ull cbB = fma2(xp1, wxB[1], z64);                                          \
    caB = fma2(xp2, wxB[2], caB);                                              \
    cbB = fma2(xp3, wxB[3], cbB);                                              \
    caB = fma2(xp4, wxB[4], caB);                                              \
    cbB = fma2(xp5, wxB[5], cbB);                                              \
    caB = fma2(xp6, wxB[6], caB);                                              \
    float sB0, sB1, sB2, sB3;                                                  \
    upk(caB, sB0, sB1); upk(cbB, sB2, sB3);                                    \
    sA0 = fmaf(hk[0],  whA[0],  sA0);  sB0 = fmaf(hk[0],  whB[0],  sB0);       \
    sA1 = fmaf(hk[1],  whA[1],  sA1);  sB1 = fmaf(hk[1],  whB[1],  sB1);       \
    sA2 = fmaf(hk[2],  whA[2],  sA2);  sB2 = fmaf(hk[2],  whB[2],  sB2);       \
    sA3 = fmaf(hk[3],  whA[3],  sA3);  sB3 = fmaf(hk[3],  whB[3],  sB3);       \
    sA0 = fmaf(hk[4],  whA[4],  sA0);  sB0 = fmaf(hk[4],  whB[4],  sB0);       \
    sA1 = fmaf(hk[5],  whA[5],  sA1);  sB1 = fmaf(hk[5],  whB[5],  sB1);       \
    sA2 = fmaf(hk[6],  whA[6],  sA2);  sB2 = fmaf(hk[6],  whB[6],  sB2);       \
    sA3 = fmaf(hk[7],  whA[7],  sA3);  sB3 = fmaf(hk[7],  whB[7],  sB3);       \
    sA0 = fmaf(hk[8],  whA[8],  sA0);  sB0 = fmaf(hk[8],  whB[8],  sB0);       \
    sA1 = fmaf(hk[9],  whA[9],  sA1);  sB1 = fmaf(hk[9],  whB[9],  sB1);       \
    sA2 = fmaf(hk[10], whA[10], sA2);  sB2 = fmaf(hk[10], whB[10], sB2);       \
    sA3 = fmaf(hk[11], whA[11], sA3);  sB3 = fmaf(hk[11], whB[11], sB3);       \
    sA0 = fmaf(hk[12], whA[12], sA0);  sB0 = fmaf(hk[12], whB[12], sB0);       \
    const float preA = (sA0 + sA1) + (sA2 + sA3);                              \
    const float preB = (sB0 + sB1) + (sB2 + sB3);                              \
    const float actA = fmaf(0.5f, tanhap(preA), 0.5f);                         \
    const float actB = fmaf(mB,   tanhap(preB), aB);                           \
    if (lane == 26 && (TTC) > 0) ob[(TTC) - 1] = actB;                         \
    const float fg = __shfl_sync(FULLM, actA, (lane + 13) & 31);               \
    const float og = __shfl_sync(FULLM, actB, (lane + 13) & 31);               \
    c = fmaf(fg, c, actA * actB);                                              \
    h = og * tanhap(c);                                                        \
} while (0)

    for (int t = 0; t < TT; t += 16) {
        // Half 0: prefetch rows t+8..t+15 into slots 8..15; process slots 0..7.
        #pragma unroll
        for (int r = 0; r < 8; r++)
            if (lane < 13 && t + 8 + r < TT)
                cp_async4(&xring[8 + r][lane], xb + (size_t)(t + 8 + r) * 13 + lane);
        cp_commit();
        cp_wait1();          // previous group (rows t..t+7) complete
        __syncwarp();        // one visibility sync per 8 steps
        #pragma unroll
        for (int u = 0; u < 8; u++) STEP(u, t + u);

        // Half 1: prefetch rows t+16..t+23 into slots 0..7; process slots 8..15.
        #pragma unroll
        for (int r = 0; r < 8; r++)
            if (lane < 13 && t + 16 + r < TT)
                cp_async4(&xring[r][lane], xb + (size_t)(t + 16 + r) * 13 + lane);
        cp_commit();
        cp_wait1();          // rows t+8..t+15 complete
        __syncwarp();
        #pragma unroll
        for (int u = 0; u < 8; u++) STEP(8 + u, t + 8 + u);
    }

    // Tail: ob[TT-1] = sigm(fc(h_{TT-1})) — lane 26's whB/biasB are the FC row.
    {
        float hk[13];
        #pragma unroll
        for (int k = 0; k < 13; k++) hk[k] = __shfl_sync(FULLM, h, k);
        float s0 = biasB, s1 = 0.0f, s2 = 0.0f, s3 = 0.0f;
        #pragma unroll
        for (int k = 0; k < 13; k++) {
            switch (k & 3) {
                case 0: s0 = fmaf(hk[k], whB[k], s0); break;
                case 1: s1 = fmaf(hk[k], whB[k], s1); break;
                case 2: s2 = fmaf(hk[k], whB[k], s2); break;
                case 3: s3 = fmaf(hk[k], whB[k], s3); break;
            }
        }
        const float pre  = (s0 + s1) + (s2 + s3);
        const float outv = fmaf(0.5f, tanhap(pre), 0.5f);
        if (lane == 26) ob[TT - 1] = outv;
    }
#undef STEP
}

extern "C" void kernel_launch(void* const* d_in, const int* in_sizes, int n_in,
                              void* d_out, int out_size) {
    (void)in_sizes; (void)n_in; (void)out_size;
    const float* x    = (const float*)d_in[0];
    const float* W_ih = (const float*)d_in[1];
    const float* W_hh = (const float*)d_in[2];
    const float* b_ih = (const float*)d_in[3];
    const float* b_hh = (const float*)d_in[4];
    const float* fc_w = (const float*)d_in[5];
    const float* fc_b = (const float*)d_in[6];
    float* out = (float*)d_out;

    lstm_warpseq4<<<NB, 32>>>(x, W_ih, W_hh, b_ih, b_hh, fc_w, fc_b, out);
}